// round 6
// baseline (speedup 1.0000x reference)
#include <cuda_runtime.h>
#include <cuda_bf16.h>
#include <cstdint>

// Problem: y[b,e] = relu(sum_a action[b,a] * conv_w[e,a] + conv_b[e])
// out[b,e,h,w] = y[b,e] broadcast over 64x64 spatial.
// B=128, A=256, E=256, H=W=64. Output fp32, 512 MB -> pure HBM-write-bound.
//
// Champion shape (one block per plane, 8 warps redundant dot, 4x STG.128
// per thread). Store-hint A/B round 3 of 3: __stwt (write-through) vs
// write-back (72.9us, 82.6% DRAM) vs __stcs (73.6us, 81.8% DRAM).

#define B_DIM   128
#define A_DIM   256
#define E_DIM   256
#define HW      4096                 // 64*64
#define NPLANES (B_DIM * E_DIM)      // 32768

__global__ __launch_bounds__(256)
void fused_embed_fill_kernel(const float*  __restrict__ action,
                             const float*  __restrict__ conv_w,
                             const float*  __restrict__ conv_b,
                             float4*       __restrict__ out)
{
    const int plane = blockIdx.x;          // b*256 + e
    const int b = plane >> 8;
    const int e = plane & 255;
    const int t    = threadIdx.x;
    const int lane = t & 31;

    // --- per-warp redundant dot product over A=256 -------------------------
    const float4* a4 = reinterpret_cast<const float4*>(action + b * A_DIM);
    const float4* w4 = reinterpret_cast<const float4*>(conv_w + e * A_DIM);

    float4 av0 = a4[lane];
    float4 av1 = a4[lane + 32];
    float4 wv0 = w4[lane];
    float4 wv1 = w4[lane + 32];

    float s;
    s = av0.x * wv0.x;
    s = fmaf(av0.y, wv0.y, s);
    s = fmaf(av0.z, wv0.z, s);
    s = fmaf(av0.w, wv0.w, s);
    s = fmaf(av1.x, wv1.x, s);
    s = fmaf(av1.y, wv1.y, s);
    s = fmaf(av1.z, wv1.z, s);
    s = fmaf(av1.w, wv1.w, s);

    s += __shfl_xor_sync(0xFFFFFFFF, s, 16);
    s += __shfl_xor_sync(0xFFFFFFFF, s, 8);
    s += __shfl_xor_sync(0xFFFFFFFF, s, 4);
    s += __shfl_xor_sync(0xFFFFFFFF, s, 2);
    s += __shfl_xor_sync(0xFFFFFFFF, s, 1);

    const float v = fmaxf(s + __ldg(conv_b + e), 0.0f);
    const float4 v4 = make_float4(v, v, v, v);

    // --- stream 16 KB plane fill (write-through stores) ---------------------
    float4* p = out + (size_t)plane * (HW / 4);   // 1024 float4 per plane

    __stwt(p + t,        v4);
    __stwt(p + t + 256,  v4);
    __stwt(p + t + 512,  v4);
    __stwt(p + t + 768,  v4);
}

extern "C" void kernel_launch(void* const* d_in, const int* in_sizes, int n_in,
                              void* d_out, int out_size)
{
    const float* action = (const float*)d_in[0];   // [128, 256]
    const float* conv_w = (const float*)d_in[1];   // [256, 256]
    const float* conv_b = (const float*)d_in[2];   // [256]
    float4* out = (float4*)d_out;                  // [128, 256, 64, 64] fp32

    fused_embed_fill_kernel<<<NPLANES, 256>>>(action, conv_w, conv_b, out);
}

// round 7
// speedup vs baseline: 1.0134x; 1.0134x over previous
#include <cuda_runtime.h>
#include <cuda_bf16.h>
#include <cstdint>

// Problem: y[b,e] = relu(sum_a action[b,a] * conv_w[e,a] + conv_b[e])
// out[b,e,h,w] = y[b,e] broadcast over 64x64 spatial.
// B=128, A=256, E=256, H=W=64. Output fp32, 512 MB -> pure HBM-write-bound.
//
// Champion shape (one block per plane, 8 warps redundant dot). Store path
// upgraded to 256-bit stores (st.global.v8.f32, sm_100+): 2 STG.256 per
// thread instead of 4 STG.128. Write-back policy (best of {wb,cs,wt} A/B).

#define B_DIM   128
#define A_DIM   256
#define E_DIM   256
#define HW      4096                 // 64*64
#define NPLANES (B_DIM * E_DIM)      // 32768

__device__ __forceinline__ void stg256(float* p, float v)
{
    asm volatile(
        "st.global.v8.f32 [%0], {%1,%1,%1,%1,%1,%1,%1,%1};"
        :: "l"(p), "f"(v) : "memory");
}

__global__ __launch_bounds__(256)
void fused_embed_fill_kernel(const float*  __restrict__ action,
                             const float*  __restrict__ conv_w,
                             const float*  __restrict__ conv_b,
                             float*        __restrict__ out)
{
    const int plane = blockIdx.x;          // b*256 + e
    const int b = plane >> 8;
    const int e = plane & 255;
    const int t    = threadIdx.x;
    const int lane = t & 31;

    // --- per-warp redundant dot product over A=256 -------------------------
    const float4* a4 = reinterpret_cast<const float4*>(action + b * A_DIM);
    const float4* w4 = reinterpret_cast<const float4*>(conv_w + e * A_DIM);

    float4 av0 = a4[lane];
    float4 av1 = a4[lane + 32];
    float4 wv0 = w4[lane];
    float4 wv1 = w4[lane + 32];

    float s;
    s = av0.x * wv0.x;
    s = fmaf(av0.y, wv0.y, s);
    s = fmaf(av0.z, wv0.z, s);
    s = fmaf(av0.w, wv0.w, s);
    s = fmaf(av1.x, wv1.x, s);
    s = fmaf(av1.y, wv1.y, s);
    s = fmaf(av1.z, wv1.z, s);
    s = fmaf(av1.w, wv1.w, s);

    s += __shfl_xor_sync(0xFFFFFFFF, s, 16);
    s += __shfl_xor_sync(0xFFFFFFFF, s, 8);
    s += __shfl_xor_sync(0xFFFFFFFF, s, 4);
    s += __shfl_xor_sync(0xFFFFFFFF, s, 2);
    s += __shfl_xor_sync(0xFFFFFFFF, s, 1);

    const float v = fmaxf(s + __ldg(conv_b + e), 0.0f);

    // --- fill this plane: 4096 floats = 512 x 32B chunks --------------------
    // Thread t writes chunks t and t+256 (each 8 floats, 32B-aligned).
    float* p = out + (size_t)plane * HW + t * 8;

    stg256(p,            v);
    stg256(p + 256 * 8,  v);
}

extern "C" void kernel_launch(void* const* d_in, const int* in_sizes, int n_in,
                              void* d_out, int out_size)
{
    const float* action = (const float*)d_in[0];   // [128, 256]
    const float* conv_w = (const float*)d_in[1];   // [256, 256]
    const float* conv_b = (const float*)d_in[2];   // [256]
    float* out = (float*)d_out;                    // [128, 256, 64, 64] fp32

    fused_embed_fill_kernel<<<NPLANES, 256>>>(action, conv_w, conv_b, out);
}